// round 1
// baseline (speedup 1.0000x reference)
#include <cuda_runtime.h>
#include <math.h>

#define BB 8
#define CIN 512
#define NPIX 4096
#define CKD 64
#define COUT 128
#define HP 66
#define PLANE (HP*HP)   /* 4356 */
#define KCONV 4608      /* 512*9 */

// ---------------- scratch (device globals; no allocation) ----------------
__device__ float g_Q[BB*CKD*NPIX];                 // [b][k][n] normalized q
__device__ float g_K[BB*CKD*NPIX];                 // [b][k][n] normalized k
__device__ float g_V[(size_t)BB*CIN*NPIX];         // [b][c][n] relu(v)
__device__ float g_simP[BB*8*CIN*CKD];             // split-K partials
__device__ float g_simT[BB*CIN*CKD];               // [b][c][k]
__device__ float g_Wos[BB*CIN*CKD];                // [b][o][k] = Wo @ simT
__device__ float g_fusep[(size_t)BB*CIN*PLANE];    // zero-padded fuse [b][c][66][66]

// ================= K1: QK GEMM + per-pixel L2 normalization =================
// C[128,4096] = [Wq;Wk] @ X[b], then affine, then L2 norm over 64 channels per pixel.
__global__ __launch_bounds__(256) void qk_kernel(
    const float* __restrict__ x,
    const float* __restrict__ wq, const float* __restrict__ sq, const float* __restrict__ bq,
    const float* __restrict__ wk, const float* __restrict__ sk, const float* __restrict__ bk)
{
    __shared__ __align__(16) float As[16][128];
    __shared__ __align__(16) float Bs[16][64];
    __shared__ float Cs[128][64];
    const int b = blockIdx.y;
    const int col0 = blockIdx.x * 64;
    const float* X = x + (size_t)b * CIN * NPIX;
    const int t = threadIdx.x;
    const int tr = t >> 4, tc = t & 15;
    float acc[8][4];
    #pragma unroll
    for (int i = 0; i < 8; i++)
        #pragma unroll
        for (int j = 0; j < 4; j++) acc[i][j] = 0.f;

    for (int kb = 0; kb < CIN; kb += 16) {
        #pragma unroll
        for (int q = 0; q < 2; q++) {
            int idx = t * 2 + q;
            int row = idx >> 2;
            int k4  = (idx & 3) << 2;
            const float* ar = (row < 64) ? (wq + row * CIN) : (wk + (row - 64) * CIN);
            float4 v4 = *reinterpret_cast<const float4*>(ar + kb + k4);
            As[k4+0][row] = v4.x; As[k4+1][row] = v4.y;
            As[k4+2][row] = v4.z; As[k4+3][row] = v4.w;
        }
        {
            int kk = t >> 4;
            int n4 = (t & 15) << 2;
            *reinterpret_cast<float4*>(&Bs[kk][n4]) =
                *reinterpret_cast<const float4*>(X + (size_t)(kb + kk) * NPIX + col0 + n4);
        }
        __syncthreads();
        #pragma unroll
        for (int kk = 0; kk < 16; kk++) {
            float4 a0 = *reinterpret_cast<float4*>(&As[kk][tr*8]);
            float4 a1 = *reinterpret_cast<float4*>(&As[kk][tr*8+4]);
            float4 b0 = *reinterpret_cast<float4*>(&Bs[kk][tc*4]);
            float av[8] = {a0.x,a0.y,a0.z,a0.w,a1.x,a1.y,a1.z,a1.w};
            float bv[4] = {b0.x,b0.y,b0.z,b0.w};
            #pragma unroll
            for (int i = 0; i < 8; i++)
                #pragma unroll
                for (int j = 0; j < 4; j++)
                    acc[i][j] = fmaf(av[i], bv[j], acc[i][j]);
        }
        __syncthreads();
    }
    #pragma unroll
    for (int i = 0; i < 8; i++) {
        int row = tr * 8 + i;
        float s, bi;
        if (row < 64) { s = sq[row]; bi = bq[row]; }
        else          { s = sk[row - 64]; bi = bk[row - 64]; }
        #pragma unroll
        for (int j = 0; j < 4; j++)
            Cs[row][tc*4 + j] = fmaf(acc[i][j], s, bi);
    }
    __syncthreads();
    if (t < 128) {
        int col  = t & 63;
        int half = t >> 6;
        float ssum = 0.f;
        #pragma unroll 8
        for (int r = 0; r < 64; r++) {
            float v = Cs[half*64 + r][col];
            ssum = fmaf(v, v, ssum);
        }
        float inv = 1.f / fmaxf(sqrtf(ssum), 1e-12f);
        float* dst = (half == 0 ? g_Q : g_K) + (size_t)b * CKD * NPIX + col0 + col;
        for (int r = 0; r < 64; r++)
            dst[(size_t)r * NPIX] = Cs[half*64 + r][col] * inv;
    }
}

// ================= K2: V = relu(affine(Wv @ X)) =================
__global__ __launch_bounds__(256) void v_kernel(
    const float* __restrict__ x, const float* __restrict__ wv,
    const float* __restrict__ sv, const float* __restrict__ bv)
{
    __shared__ __align__(16) float As[16][128];
    __shared__ __align__(16) float Bs[16][64];
    const int b = blockIdx.z;
    const int row0 = blockIdx.y * 128;
    const int col0 = blockIdx.x * 64;
    const float* X = x + (size_t)b * CIN * NPIX;
    const int t = threadIdx.x;
    const int tr = t >> 4, tc = t & 15;
    float acc[8][4];
    #pragma unroll
    for (int i = 0; i < 8; i++)
        #pragma unroll
        for (int j = 0; j < 4; j++) acc[i][j] = 0.f;

    for (int kb = 0; kb < CIN; kb += 16) {
        #pragma unroll
        for (int q = 0; q < 2; q++) {
            int idx = t * 2 + q;
            int row = idx >> 2;
            int k4  = (idx & 3) << 2;
            float4 v4 = *reinterpret_cast<const float4*>(wv + (size_t)(row0 + row) * CIN + kb + k4);
            As[k4+0][row] = v4.x; As[k4+1][row] = v4.y;
            As[k4+2][row] = v4.z; As[k4+3][row] = v4.w;
        }
        {
            int kk = t >> 4;
            int n4 = (t & 15) << 2;
            *reinterpret_cast<float4*>(&Bs[kk][n4]) =
                *reinterpret_cast<const float4*>(X + (size_t)(kb + kk) * NPIX + col0 + n4);
        }
        __syncthreads();
        #pragma unroll
        for (int kk = 0; kk < 16; kk++) {
            float4 a0 = *reinterpret_cast<float4*>(&As[kk][tr*8]);
            float4 a1 = *reinterpret_cast<float4*>(&As[kk][tr*8+4]);
            float4 b0 = *reinterpret_cast<float4*>(&Bs[kk][tc*4]);
            float av[8] = {a0.x,a0.y,a0.z,a0.w,a1.x,a1.y,a1.z,a1.w};
            float bv4[4] = {b0.x,b0.y,b0.z,b0.w};
            #pragma unroll
            for (int i = 0; i < 8; i++)
                #pragma unroll
                for (int j = 0; j < 4; j++)
                    acc[i][j] = fmaf(av[i], bv4[j], acc[i][j]);
        }
        __syncthreads();
    }
    #pragma unroll
    for (int i = 0; i < 8; i++) {
        int row = row0 + tr * 8 + i;
        float s = sv[row], bi = bv[row];
        float4 o;
        o.x = fmaxf(fmaf(acc[i][0], s, bi), 0.f);
        o.y = fmaxf(fmaf(acc[i][1], s, bi), 0.f);
        o.z = fmaxf(fmaf(acc[i][2], s, bi), 0.f);
        o.w = fmaxf(fmaf(acc[i][3], s, bi), 0.f);
        *reinterpret_cast<float4*>(g_V + (size_t)b * CIN * NPIX + (size_t)row * NPIX + col0 + tc*4) = o;
    }
}

// ================= K3: simT partials: V[b] @ K[b]^T (split over n) =================
__global__ __launch_bounds__(256) void sim_kernel()
{
    __shared__ __align__(16) float As[16][64];  // [n][c]
    __shared__ __align__(16) float Bs[16][64];  // [n][k]
    const int b = blockIdx.z, chunk = blockIdx.y;
    const int row0 = blockIdx.x * 64;
    const float* V  = g_V + (size_t)b * CIN * NPIX;
    const float* Km = g_K + (size_t)b * CKD * NPIX;
    const int t = threadIdx.x;
    const int tr = t >> 4, tc = t & 15;
    float acc[4][4];
    #pragma unroll
    for (int i = 0; i < 4; i++)
        #pragma unroll
        for (int j = 0; j < 4; j++) acc[i][j] = 0.f;

    const int nb0 = chunk * 512;
    for (int nb = nb0; nb < nb0 + 512; nb += 16) {
        {
            int r  = t >> 2;          // 0..63
            int n4 = (t & 3) << 2;
            float4 va = *reinterpret_cast<const float4*>(V  + (size_t)(row0 + r) * NPIX + nb + n4);
            As[n4+0][r] = va.x; As[n4+1][r] = va.y; As[n4+2][r] = va.z; As[n4+3][r] = va.w;
            float4 vb = *reinterpret_cast<const float4*>(Km + (size_t)r * NPIX + nb + n4);
            Bs[n4+0][r] = vb.x; Bs[n4+1][r] = vb.y; Bs[n4+2][r] = vb.z; Bs[n4+3][r] = vb.w;
        }
        __syncthreads();
        #pragma unroll
        for (int nn = 0; nn < 16; nn++) {
            float4 a = *reinterpret_cast<float4*>(&As[nn][tr*4]);
            float4 bb = *reinterpret_cast<float4*>(&Bs[nn][tc*4]);
            float av[4] = {a.x,a.y,a.z,a.w};
            float bv[4] = {bb.x,bb.y,bb.z,bb.w};
            #pragma unroll
            for (int i = 0; i < 4; i++)
                #pragma unroll
                for (int j = 0; j < 4; j++)
                    acc[i][j] = fmaf(av[i], bv[j], acc[i][j]);
        }
        __syncthreads();
    }
    #pragma unroll
    for (int i = 0; i < 4; i++) {
        int c = row0 + tr * 4 + i;
        float4 o = make_float4(acc[i][0], acc[i][1], acc[i][2], acc[i][3]);
        *reinterpret_cast<float4*>(g_simP + ((size_t)(b*8 + chunk) * CIN + c) * CKD + tc*4) = o;
    }
}

// ================= K3b: deterministic split-K reduce =================
__global__ __launch_bounds__(256) void sim_reduce()
{
    int idx = blockIdx.x * 256 + threadIdx.x;
    if (idx >= BB * CIN * CKD) return;
    int b = idx / (CIN * CKD);
    int rem = idx - b * CIN * CKD;
    float s = 0.f;
    #pragma unroll
    for (int p = 0; p < 8; p++)
        s += g_simP[(size_t)(b*8 + p) * CIN * CKD + rem];
    g_simT[idx] = s;
}

// ================= K4: Wos[b] = Wo @ simT[b]  (512x64, K=512) =================
__global__ __launch_bounds__(256) void wos_kernel(const float* __restrict__ wo)
{
    __shared__ __align__(16) float As[16][64];
    __shared__ __align__(16) float Bs[16][64];
    const int b = blockIdx.y;
    const int row0 = blockIdx.x * 64;
    const float* ST = g_simT + (size_t)b * CIN * CKD;
    const int t = threadIdx.x;
    const int tr = t >> 4, tc = t & 15;
    float acc[4][4];
    #pragma unroll
    for (int i = 0; i < 4; i++)
        #pragma unroll
        for (int j = 0; j < 4; j++) acc[i][j] = 0.f;

    for (int kb = 0; kb < CIN; kb += 16) {
        {
            int r  = t >> 2;
            int k4 = (t & 3) << 2;
            float4 va = *reinterpret_cast<const float4*>(wo + (size_t)(row0 + r) * CIN + kb + k4);
            As[k4+0][r] = va.x; As[k4+1][r] = va.y; As[k4+2][r] = va.z; As[k4+3][r] = va.w;
            int kk = t >> 4;
            int n4 = (t & 15) << 2;
            *reinterpret_cast<float4*>(&Bs[kk][n4]) =
                *reinterpret_cast<const float4*>(ST + (size_t)(kb + kk) * CKD + n4);
        }
        __syncthreads();
        #pragma unroll
        for (int kk = 0; kk < 16; kk++) {
            float4 a = *reinterpret_cast<float4*>(&As[kk][tr*4]);
            float4 bb = *reinterpret_cast<float4*>(&Bs[kk][tc*4]);
            float av[4] = {a.x,a.y,a.z,a.w};
            float bv[4] = {bb.x,bb.y,bb.z,bb.w};
            #pragma unroll
            for (int i = 0; i < 4; i++)
                #pragma unroll
                for (int j = 0; j < 4; j++)
                    acc[i][j] = fmaf(av[i], bv[j], acc[i][j]);
        }
        __syncthreads();
    }
    #pragma unroll
    for (int i = 0; i < 4; i++) {
        int o = row0 + tr * 4 + i;
        float4 ov = make_float4(acc[i][0], acc[i][1], acc[i][2], acc[i][3]);
        *reinterpret_cast<float4*>(g_Wos + (size_t)b * CIN * CKD + (size_t)o * CKD + tc*4) = ov;
    }
}

// ================= K0: zero the borders of the padded fuse buffer =================
__global__ __launch_bounds__(256) void zero_border()
{
    int idx = blockIdx.x * 256 + threadIdx.x;
    if (idx >= BB * CIN * HP) return;
    int plane = idx / HP;
    int i = idx - plane * HP;
    float* p = g_fusep + (size_t)plane * PLANE;
    p[i] = 0.f;               // top row
    p[65*HP + i] = 0.f;       // bottom row
    p[i*HP] = 0.f;            // left col
    p[i*HP + 65] = 0.f;       // right col
}

// ================= K5: fuse = relu(affine(Wos @ Q)) + x + up -> padded layout ====
__global__ __launch_bounds__(256) void fuse_kernel(
    const float* __restrict__ x, const float* __restrict__ up,
    const float* __restrict__ so, const float* __restrict__ bo)
{
    __shared__ __align__(16) float As[16][128];
    __shared__ __align__(16) float Bs[16][64];
    const int b = blockIdx.z;
    const int row0 = blockIdx.y * 128;
    const int h = blockIdx.x;
    const int col0 = h * 64;
    const float* Wos = g_Wos + (size_t)b * CIN * CKD;
    const float* Qm  = g_Q   + (size_t)b * CKD * NPIX;
    const int t = threadIdx.x;
    const int tr = t >> 4, tc = t & 15;
    float acc[8][4];
    #pragma unroll
    for (int i = 0; i < 8; i++)
        #pragma unroll
        for (int j = 0; j < 4; j++) acc[i][j] = 0.f;

    for (int kb = 0; kb < CKD; kb += 16) {
        #pragma unroll
        for (int q = 0; q < 2; q++) {
            int idx = t * 2 + q;
            int row = idx >> 2;
            int k4  = (idx & 3) << 2;
            float4 v4 = *reinterpret_cast<const float4*>(Wos + (size_t)(row0 + row) * CKD + kb + k4);
            As[k4+0][row] = v4.x; As[k4+1][row] = v4.y;
            As[k4+2][row] = v4.z; As[k4+3][row] = v4.w;
        }
        {
            int kk = t >> 4;
            int n4 = (t & 15) << 2;
            *reinterpret_cast<float4*>(&Bs[kk][n4]) =
                *reinterpret_cast<const float4*>(Qm + (size_t)(kb + kk) * NPIX + col0 + n4);
        }
        __syncthreads();
        #pragma unroll
        for (int kk = 0; kk < 16; kk++) {
            float4 a0 = *reinterpret_cast<float4*>(&As[kk][tr*8]);
            float4 a1 = *reinterpret_cast<float4*>(&As[kk][tr*8+4]);
            float4 b0 = *reinterpret_cast<float4*>(&Bs[kk][tc*4]);
            float av[8] = {a0.x,a0.y,a0.z,a0.w,a1.x,a1.y,a1.z,a1.w};
            float bv[4] = {b0.x,b0.y,b0.z,b0.w};
            #pragma unroll
            for (int i = 0; i < 8; i++)
                #pragma unroll
                for (int j = 0; j < 4; j++)
                    acc[i][j] = fmaf(av[i], bv[j], acc[i][j]);
        }
        __syncthreads();
    }
    #pragma unroll
    for (int i = 0; i < 8; i++) {
        int row = row0 + tr * 8 + i;
        float s = so[row], bi = bo[row];
        size_t xoff = (size_t)b * CIN * NPIX + (size_t)row * NPIX + col0 + tc*4;
        float4 xv = *reinterpret_cast<const float4*>(x + xoff);
        float4 uv = *reinterpret_cast<const float4*>(up + xoff);
        float* dst = g_fusep + ((size_t)b * CIN + row) * PLANE + (h + 1) * HP + 1 + tc*4;
        dst[0] = fmaxf(fmaf(acc[i][0], s, bi), 0.f) + xv.x + uv.x;
        dst[1] = fmaxf(fmaf(acc[i][1], s, bi), 0.f) + xv.y + uv.y;
        dst[2] = fmaxf(fmaf(acc[i][2], s, bi), 0.f) + xv.z + uv.z;
        dst[3] = fmaxf(fmaf(acc[i][3], s, bi), 0.f) + xv.w + uv.w;
    }
}

// ================= K6: 3x3 conv as implicit GEMM [128,4608]@[4608,64] per row ====
__global__ __launch_bounds__(256) void conv_kernel(
    const float* __restrict__ wsm, const float* __restrict__ ssc,
    const float* __restrict__ bsc, float* __restrict__ out)
{
    __shared__ __align__(16) float As[16][128];
    __shared__ float Bs[16][64];
    const int h = blockIdx.x, b = blockIdx.y;
    const int t = threadIdx.x;
    const int tr = t >> 4, tc = t & 15;
    float acc[8][4];
    #pragma unroll
    for (int i = 0; i < 8; i++)
        #pragma unroll
        for (int j = 0; j < 4; j++) acc[i][j] = 0.f;

    const float* fbase = g_fusep + (size_t)b * CIN * PLANE;
    for (int kb = 0; kb < KCONV; kb += 16) {
        #pragma unroll
        for (int q = 0; q < 2; q++) {
            int idx = t * 2 + q;
            int row = idx >> 2;
            int k4  = (idx & 3) << 2;
            float4 v4 = *reinterpret_cast<const float4*>(wsm + (size_t)row * KCONV + kb + k4);
            As[k4+0][row] = v4.x; As[k4+1][row] = v4.y;
            As[k4+2][row] = v4.z; As[k4+3][row] = v4.w;
        }
        {
            int kk = t >> 4;
            int w0 = (t & 15) << 2;
            int k  = kb + kk;
            int ic = k / 9;
            int r9 = k - ic * 9;
            int dy = r9 / 3;
            int dx = r9 - dy * 3;
            const float* src = fbase + (size_t)ic * PLANE + (h + dy) * HP + dx + w0;
            Bs[kk][w0+0] = src[0];
            Bs[kk][w0+1] = src[1];
            Bs[kk][w0+2] = src[2];
            Bs[kk][w0+3] = src[3];
        }
        __syncthreads();
        #pragma unroll
        for (int kk = 0; kk < 16; kk++) {
            float4 a0 = *reinterpret_cast<float4*>(&As[kk][tr*8]);
            float4 a1 = *reinterpret_cast<float4*>(&As[kk][tr*8+4]);
            float4 b0 = *reinterpret_cast<float4*>(&Bs[kk][tc*4]);
            float av[8] = {a0.x,a0.y,a0.z,a0.w,a1.x,a1.y,a1.z,a1.w};
            float bv[4] = {b0.x,b0.y,b0.z,b0.w};
            #pragma unroll
            for (int i = 0; i < 8; i++)
                #pragma unroll
                for (int j = 0; j < 4; j++)
                    acc[i][j] = fmaf(av[i], bv[j], acc[i][j]);
        }
        __syncthreads();
    }
    #pragma unroll
    for (int i = 0; i < 8; i++) {
        int oc = tr * 8 + i;
        float s = ssc[oc], bi = bsc[oc];
        float4 o;
        o.x = fmaxf(fmaf(acc[i][0], s, bi), 0.f);
        o.y = fmaxf(fmaf(acc[i][1], s, bi), 0.f);
        o.z = fmaxf(fmaf(acc[i][2], s, bi), 0.f);
        o.w = fmaxf(fmaf(acc[i][3], s, bi), 0.f);
        *reinterpret_cast<float4*>(out + ((size_t)(b * COUT + oc)) * NPIX + h * 64 + tc*4) = o;
    }
}

// ================= launch =================
extern "C" void kernel_launch(void* const* d_in, const int* in_sizes, int n_in,
                              void* d_out, int out_size)
{
    const float* x  = (const float*)d_in[0];
    const float* up = (const float*)d_in[1];
    const float* wq = (const float*)d_in[2];
    const float* sq = (const float*)d_in[3];
    const float* bq = (const float*)d_in[4];
    const float* wk = (const float*)d_in[5];
    const float* sk = (const float*)d_in[6];
    const float* bk = (const float*)d_in[7];
    const float* wv = (const float*)d_in[8];
    const float* sv = (const float*)d_in[9];
    const float* bv = (const float*)d_in[10];
    const float* wo = (const float*)d_in[11];
    const float* so = (const float*)d_in[12];
    const float* bo = (const float*)d_in[13];
    const float* ws = (const float*)d_in[14];
    const float* ss = (const float*)d_in[15];
    const float* bs = (const float*)d_in[16];
    float* out = (float*)d_out;

    qk_kernel<<<dim3(64, 8), 256>>>(x, wq, sq, bq, wk, sk, bk);
    v_kernel<<<dim3(64, 4, 8), 256>>>(x, wv, sv, bv);
    sim_kernel<<<dim3(8, 8, 8), 256>>>();
    sim_reduce<<<(BB * CIN * CKD + 255) / 256, 256>>>();
    wos_kernel<<<dim3(8, 8), 256>>>(wo);
    zero_border<<<(BB * CIN * HP + 255) / 256, 256>>>();
    fuse_kernel<<<dim3(64, 4, 8), 256>>>(x, up, so, bo);
    conv_kernel<<<dim3(64, 8), 256>>>(ws, ss, bs, out);
}